// round 6
// baseline (speedup 1.0000x reference)
#include <cuda_runtime.h>
#include <math.h>

// Problem dims
#define BATCH 512
#define TT    512
#define DD    128   // input / decoder hidden
#define HH    64    // encoder hidden

// Encoder: gates 4H=256, K = D+H = 192 (concatenated [Wih_e | Whh_e])
#define GE 256
#define KE 192
// Decoder: gates 4D=512, K = D = 128
#define GD 512
#define KD 128

// ---------------- device scratch (static: no allocation) ----------------
__device__ __align__(16) float g_Wenc_t[KE * GE];      // [k][j], k<128 from Wih_e, k>=128 from Whh_e
__device__ __align__(16) float g_Wdec_t[KD * 384];     // [k][j], gates i,f,g (j<384)
__device__ __align__(16) float g_Wo_t  [KD * 128];     // [k][jo], o-gate rows (j=384..511)
__device__ __align__(16) float g_Wihd_t[HH * GD];      // [k][j] decoder input proj, k<64
__device__ __align__(16) float g_henc  [BATCH * HH];   // encoder final hidden

__device__ __forceinline__ float sigf(float x) { return 1.0f / (1.0f + expf(-x)); }

// ---------------- prep: transpose all weights (one-time, tiny) ----------------
__global__ void prep_kernel(const float* __restrict__ Wih_e,
                            const float* __restrict__ Whh_e,
                            const float* __restrict__ Whh_d,
                            const float* __restrict__ Wih_d) {
    int idx = blockIdx.x * 256 + threadIdx.x;            // 0 .. 147455
    if (idx < KE * GE) {                                 // 49152: encoder concat
        int k = idx >> 8, j = idx & 255;
        g_Wenc_t[idx] = (k < 128) ? Wih_e[j * 128 + k] : Whh_e[j * 64 + (k - 128)];
        return;
    }
    int i2 = idx - KE * GE;
    if (i2 < KD * 384) {                                 // 49152: decoder i,f,g
        int k = i2 / 384, j = i2 % 384;
        g_Wdec_t[i2] = Whh_d[j * 128 + k];
        return;
    }
    int i3 = i2 - KD * 384;
    if (i3 < KD * 128) {                                 // 16384: decoder o-gate
        int k = i3 >> 7, j = i3 & 127;
        g_Wo_t[i3] = Whh_d[(384 + j) * 128 + k];
        return;
    }
    int i4 = i3 - KD * 128;
    if (i4 < HH * GD) {                                  // 32768: decoder input proj
        int k = i4 >> 9, j = i4 & 511;
        g_Wihd_t[i4] = Wih_d[j * 64 + k];
    }
}

// ---------------- encoder: fused input-projection + recurrence ----------------
// grid 128 CTAs x 4 batch rows, 256 threads. SMEM:
//   Wt  [192][256]  196608 B
//   inp [192][4]      3072 B   (k-major: [x_t(128) ; h(64)] per batch row)
//   g   [4][256]      4096 B
//   bias[256]         1024 B
#define ENC_SMEM_FLOATS (KE*GE + KE*4 + 4*GE + GE)
#define ENC_SMEM_BYTES  (ENC_SMEM_FLOATS * 4)

__global__ __launch_bounds__(256, 1)
void enc_kernel(const float* __restrict__ x, const float* __restrict__ b_e) {
    extern __shared__ float sm[];
    float* Wt   = sm;                       // 49152
    float* inp  = sm + KE * GE;             // 768
    float* gbuf = inp + KE * 4;             // 1024
    float* bias = gbuf + 4 * GE;            // 256

    const int tid = threadIdx.x;
    const int bb  = blockIdx.x * 4;

    // load weights (coalesced, conflict-free: layout already transposed)
    {
        const float4* src = (const float4*)g_Wenc_t;
        float4* dst = (float4*)Wt;
        #pragma unroll 4
        for (int i = tid; i < (KE * GE) / 4; i += 256) dst[i] = src[i];
    }
    bias[tid] = b_e[tid];

    // init inp: x_0 in k=[0,128), h=0 in k=[128,192)
    {
        int b = tid >> 6, kk = (tid & 63) * 2;
        float2 v = *(const float2*)&x[(size_t)(bb + b) * TT * DD + kk];
        inp[kk * 4 + b]       = v.x;
        inp[(kk + 1) * 4 + b] = v.y;
        inp[(128 + (tid >> 2)) * 4 + (tid & 3)] = 0.0f;
    }
    float c_reg = 0.0f;
    const int eb = tid >> 6, ej = tid & 63;   // elementwise identity: owns cell (eb, ej)
    __syncthreads();

    for (int t = 0; t < TT; ++t) {
        // prefetch x_{t+1} (issue LDG early; consumed after the compute loop)
        float2 xpre = make_float2(0.0f, 0.0f);
        const int pb = tid >> 6, pk = (tid & 63) * 2;
        if (t + 1 < TT)
            xpre = *(const float2*)&x[(size_t)(bb + pb) * TT * DD + (size_t)(t + 1) * DD + pk];

        // gate GEMM: thread j computes gates[j] for 4 batch rows
        const int j = tid;
        float a0 = bias[j], a1 = a0, a2 = a0, a3 = a0;
        #pragma unroll 4
        for (int k = 0; k < KE; ++k) {
            float  w  = Wt[k * GE + j];           // lanes: consecutive j, conflict-free
            float4 iv = *(float4*)&inp[k * 4];    // broadcast
            a0 = fmaf(w, iv.x, a0);
            a1 = fmaf(w, iv.y, a1);
            a2 = fmaf(w, iv.z, a2);
            a3 = fmaf(w, iv.w, a3);
        }
        gbuf[0 * GE + j] = a0; gbuf[1 * GE + j] = a1;
        gbuf[2 * GE + j] = a2; gbuf[3 * GE + j] = a3;
        __syncthreads();

        // elementwise LSTM cell (PyTorch gate order i,f,g,o)
        float gi = gbuf[eb * GE + ej];
        float gf = gbuf[eb * GE + 64 + ej];
        float gg = gbuf[eb * GE + 128 + ej];
        float go = gbuf[eb * GE + 192 + ej];
        float i_ = sigf(gi), f_ = sigf(gf), g_ = tanhf(gg), o_ = sigf(go);
        c_reg = f_ * c_reg + i_ * g_;
        float h_ = o_ * tanhf(c_reg);
        inp[(128 + ej) * 4 + eb] = h_;
        // commit prefetched x_{t+1}
        inp[pk * 4 + pb]       = xpre.x;
        inp[(pk + 1) * 4 + pb] = xpre.y;
        __syncthreads();

        if (t == TT - 1) g_henc[(bb + eb) * HH + ej] = h_;
    }
}

// ---------------- decoder: const-input recurrence, full output sequence ----------------
// grid 128 CTAs x 4 batch rows, 512 threads. SMEM:
//   Wd  [128][384]  196608 B  (i,f,g gate weights)
//   xp  [4][512]      8192 B  (constant per-step gate bias: Wih_d·h_enc + b_d)
//   g   [4][512]      8192 B
//   hsm [128][4]      2048 B
#define DEC_SMEM_FLOATS (KD*384 + 4*GD + 4*GD + KD*4)
#define DEC_SMEM_BYTES  (DEC_SMEM_FLOATS * 4)

__global__ __launch_bounds__(512, 1)
void dec_kernel(const float* __restrict__ b_d, float* __restrict__ out) {
    extern __shared__ float sm[];
    float* Wd   = sm;                 // 49152
    float* xp   = sm + KD * 384;      // 2048
    float* gbuf = xp + 4 * GD;        // 2048
    float* hsm  = gbuf + 4 * GD;      // 512

    const int tid = threadIdx.x;
    const int bb  = blockIdx.x * 4;

    {
        const float4* src = (const float4*)g_Wdec_t;
        float4* dst = (float4*)Wd;
        #pragma unroll 4
        for (int i = tid; i < (KD * 384) / 4; i += 512) dst[i] = src[i];
    }
    // stage h_enc[4][64] temporarily in gbuf[0..255]
    if (tid < 256) gbuf[tid] = g_henc[(bb + (tid >> 6)) * HH + (tid & 63)];
    hsm[tid < 512 ? tid : 0] = 0.0f;   // h_0 = 0 (512 threads cover 512 floats)
    __syncthreads();

    // one-time input projection: xp[b][j] = b_d[j] + sum_k Wih_d[j][k] * h_enc[b][k]
    {
        const int j = tid;
        float a0 = b_d[j], a1 = a0, a2 = a0, a3 = a0;
        #pragma unroll 4
        for (int k = 0; k < HH; ++k) {
            float w = g_Wihd_t[k * GD + j];
            a0 = fmaf(w, gbuf[0 * 64 + k], a0);
            a1 = fmaf(w, gbuf[1 * 64 + k], a1);
            a2 = fmaf(w, gbuf[2 * 64 + k], a2);
            a3 = fmaf(w, gbuf[3 * 64 + k], a3);
        }
        xp[0 * GD + j] = a0; xp[1 * GD + j] = a1;
        xp[2 * GD + j] = a2; xp[3 * GD + j] = a3;
    }
    __syncthreads();

    float c_reg = 0.0f;
    const int eb = tid >> 7, ej = tid & 127;

    for (int t = 0; t < TT; ++t) {
        if (tid < 384) {
            // i,f,g gates from SMEM weights
            const int j = tid;
            float a0 = xp[j], a1 = xp[GD + j], a2 = xp[2 * GD + j], a3 = xp[3 * GD + j];
            #pragma unroll 4
            for (int k = 0; k < KD; ++k) {
                float  w  = Wd[k * 384 + j];
                float4 hv = *(float4*)&hsm[k * 4];
                a0 = fmaf(w, hv.x, a0);
                a1 = fmaf(w, hv.y, a1);
                a2 = fmaf(w, hv.z, a2);
                a3 = fmaf(w, hv.w, a3);
            }
            gbuf[j] = a0; gbuf[GD + j] = a1; gbuf[2 * GD + j] = a2; gbuf[3 * GD + j] = a3;
        } else {
            // o-gate: weights streamed from L2 (same 64KB every step, L2-resident)
            const int jo = tid - 384;
            const int j  = 384 + jo;
            float a0 = xp[j], a1 = xp[GD + j], a2 = xp[2 * GD + j], a3 = xp[3 * GD + j];
            for (int k0 = 0; k0 < KD; k0 += 16) {
                float w[16];
                #pragma unroll
                for (int u = 0; u < 16; ++u)
                    w[u] = __ldg(&g_Wo_t[(k0 + u) * 128 + jo]);
                #pragma unroll
                for (int u = 0; u < 16; ++u) {
                    float4 hv = *(float4*)&hsm[(k0 + u) * 4];
                    a0 = fmaf(w[u], hv.x, a0);
                    a1 = fmaf(w[u], hv.y, a1);
                    a2 = fmaf(w[u], hv.z, a2);
                    a3 = fmaf(w[u], hv.w, a3);
                }
            }
            gbuf[j] = a0; gbuf[GD + j] = a1; gbuf[2 * GD + j] = a2; gbuf[3 * GD + j] = a3;
        }
        __syncthreads();

        float gi = gbuf[eb * GD + ej];
        float gf = gbuf[eb * GD + 128 + ej];
        float gg = gbuf[eb * GD + 256 + ej];
        float go = gbuf[eb * GD + 384 + ej];
        float i_ = sigf(gi), f_ = sigf(gf), g_ = tanhf(gg), o_ = sigf(go);
        c_reg = f_ * c_reg + i_ * g_;
        float h_ = o_ * tanhf(c_reg);
        hsm[ej * 4 + eb] = h_;
        out[((size_t)(bb + eb) * TT + t) * DD + ej] = h_;   // coalesced 512B rows
        __syncthreads();
    }
}

// ---------------- launch ----------------
extern "C" void kernel_launch(void* const* d_in, const int* in_sizes, int n_in,
                              void* d_out, int out_size) {
    const float* x     = (const float*)d_in[0];
    const float* Wih_e = (const float*)d_in[1];
    const float* Whh_e = (const float*)d_in[2];
    const float* b_e   = (const float*)d_in[3];
    const float* Wih_d = (const float*)d_in[4];
    const float* Whh_d = (const float*)d_in[5];
    const float* b_d   = (const float*)d_in[6];
    float* out = (float*)d_out;

    cudaFuncSetAttribute(enc_kernel, cudaFuncAttributeMaxDynamicSharedMemorySize, ENC_SMEM_BYTES);
    cudaFuncSetAttribute(dec_kernel, cudaFuncAttributeMaxDynamicSharedMemorySize, DEC_SMEM_BYTES);

    prep_kernel<<<576, 256>>>(Wih_e, Whh_e, Whh_d, Wih_d);   // 147456 elements, exact
    enc_kernel<<<BATCH / 4, 256, ENC_SMEM_BYTES>>>(x, b_e);
    dec_kernel<<<BATCH / 4, 512, DEC_SMEM_BYTES>>>(b_d, out);
}

// round 7
// speedup vs baseline: 1.1009x; 1.1009x over previous
#include <cuda_runtime.h>
#include <math.h>

// Problem dims
#define BATCH 512
#define TT    512
#define DD    128   // input / decoder hidden
#define HH    64    // encoder hidden

#define GE 256      // encoder gates 4H
#define KE 192      // encoder K = D + H (concat [Wih_e | Whh_e])
#define GD 512      // decoder gates 4D
#define KD 128      // decoder K = D

typedef unsigned long long u64t;

// ---------------- device scratch (static: no allocation) ----------------
// k-paired layout: element (k,j) at (k>>1)*G*2 + j*2 + (k&1)
__device__ __align__(16) float g_Wenc_t[KE * GE];
__device__ __align__(16) float g_Wdec_t[KD * 384];
// k-quad layout: element (k,jo) at (k>>2)*512 + jo*4 + (k&3)
__device__ __align__(16) float g_Wo4  [KD * 128];
__device__ __align__(16) float g_Wihd_t[HH * GD];   // [k][j]
__device__ __align__(16) float g_henc  [BATCH * HH];

// ---------------- f32x2 / SMEM helpers ----------------
__device__ __forceinline__ u64t d2(float a) {
    u64t r; asm("mov.b64 %0, {%1, %1};" : "=l"(r) : "f"(a)); return r;
}
__device__ __forceinline__ u64t fma2(u64t a, u64t b, u64t c) {
    asm("fma.rn.f32x2 %0, %1, %2, %3;" : "=l"(c) : "l"(a), "l"(b), "l"(c));
    return c;
}
__device__ __forceinline__ float2 unpk(u64t v) {
    float2 r; asm("mov.b64 {%0, %1}, %2;" : "=f"(r.x), "=f"(r.y) : "l"(v)); return r;
}
__device__ __forceinline__ void lds_v2u64(u64t& x, u64t& y, unsigned addr) {
    asm volatile("ld.shared.v2.u64 {%0, %1}, [%2];" : "=l"(x), "=l"(y) : "r"(addr));
}
__device__ __forceinline__ float2 lds_f2(unsigned addr) {
    float2 v; asm volatile("ld.shared.v2.f32 {%0, %1}, [%2];" : "=f"(v.x), "=f"(v.y) : "r"(addr));
    return v;
}
__device__ __forceinline__ float tanh_ap(float x) {
    asm("tanh.approx.f32 %0, %0;" : "+f"(x)); return x;
}
__device__ __forceinline__ float sig_ap(float x) {
    return fmaf(tanh_ap(0.5f * x), 0.5f, 0.5f);
}

// ---------------- prep: transpose + re-tile all weights (one-time, tiny) ----------------
__global__ void prep_kernel(const float* __restrict__ Wih_e,
                            const float* __restrict__ Whh_e,
                            const float* __restrict__ Whh_d,
                            const float* __restrict__ Wih_d) {
    int idx = blockIdx.x * 256 + threadIdx.x;            // 0 .. 147455
    if (idx < KE * GE) {                                 // encoder concat, k-paired
        int r = idx & 1, j = (idx >> 1) & 255, k2 = idx >> 9;
        int k = 2 * k2 + r;
        g_Wenc_t[idx] = (k < 128) ? Wih_e[j * 128 + k] : Whh_e[j * 64 + (k - 128)];
        return;
    }
    int i2 = idx - KE * GE;
    if (i2 < KD * 384) {                                 // decoder i,f,g, k-paired
        int r = i2 & 1, j = (i2 >> 1) % 384, k2 = i2 / 768;
        int k = 2 * k2 + r;
        g_Wdec_t[i2] = Whh_d[j * 128 + k];
        return;
    }
    int i3 = i2 - KD * 384;
    if (i3 < KD * 128) {                                 // decoder o-gate, k-quad
        int r = i3 & 3, jo = (i3 >> 2) & 127, k4 = i3 >> 9;
        int k = 4 * k4 + r;
        g_Wo4[i3] = Whh_d[(384 + jo) * 128 + k];
        return;
    }
    int i4 = i3 - KD * 128;
    if (i4 < HH * GD) {                                  // decoder input proj [k][j]
        int k = i4 >> 9, j = i4 & 511;
        g_Wihd_t[i4] = Wih_d[j * 64 + k];
    }
}

// ---------------- encoder ----------------
// 128 CTAs x 4 batch rows, 256 threads.
// SMEM: Wt[96][256]x2  196608B | inp[192][4] 3072B | gbuf[4][256] 4096B | bias 1024B
#define ENC_SMEM_FLOATS (KE*GE + KE*4 + 4*GE + GE)
#define ENC_SMEM_BYTES  (ENC_SMEM_FLOATS * 4)

__global__ __launch_bounds__(256, 1)
void enc_kernel(const float* __restrict__ x, const float* __restrict__ b_e) {
    extern __shared__ float sm[];
    float* Wt   = sm;                       // 49152 (k-paired)
    float* inp  = sm + KE * GE;             // 768  [k][b]
    float* gbuf = inp + KE * 4;             // 1024 [b][j]
    float* bias = gbuf + 4 * GE;            // 256

    const int tid = threadIdx.x;
    const int bb  = blockIdx.x * 4;

    {
        const float4* src = (const float4*)g_Wenc_t;
        float4* dst = (float4*)Wt;
        #pragma unroll 4
        for (int i = tid; i < (KE * GE) / 4; i += 256) dst[i] = src[i];
    }
    bias[tid] = b_e[tid];
    {
        int b = tid >> 6, kk = (tid & 63) * 2;
        float2 v = *(const float2*)&x[(size_t)(bb + b) * TT * DD + kk];
        inp[kk * 4 + b]       = v.x;
        inp[(kk + 1) * 4 + b] = v.y;
        inp[(128 + (tid >> 2)) * 4 + (tid & 3)] = 0.0f;
    }
    float c_reg = 0.0f;
    const int eb = tid >> 6, ej = tid & 63;
    const unsigned Wb = (unsigned)__cvta_generic_to_shared(Wt) + tid * 8;
    const unsigned Ib = (unsigned)__cvta_generic_to_shared(inp);
    __syncthreads();

    for (int t = 0; t < TT; ++t) {
        // prefetch x_{t+1}
        float2 xpre = make_float2(0.0f, 0.0f);
        const int pb = tid >> 6, pk = (tid & 63) * 2;
        if (t + 1 < TT)
            xpre = *(const float2*)&x[(size_t)(bb + pb) * TT * DD + (size_t)(t + 1) * DD + pk];

        float bj = bias[tid];
        u64t a01 = d2(bj), a23 = d2(bj);
        unsigned wa = Wb, ia = Ib;
        #pragma unroll 8
        for (int k2 = 0; k2 < 96; ++k2) {
            float2 w = lds_f2(wa);
            u64t i0a, i0b, i1a, i1b;
            lds_v2u64(i0a, i0b, ia);
            lds_v2u64(i1a, i1b, ia + 16);
            u64t w0 = d2(w.x), w1 = d2(w.y);
            a01 = fma2(w0, i0a, a01); a23 = fma2(w0, i0b, a23);
            a01 = fma2(w1, i1a, a01); a23 = fma2(w1, i1b, a23);
            wa += GE * 8;  // 2048
            ia += 32;
        }
        float2 v01 = unpk(a01), v23 = unpk(a23);
        gbuf[tid] = v01.x; gbuf[256 + tid] = v01.y;
        gbuf[512 + tid] = v23.x; gbuf[768 + tid] = v23.y;
        __syncthreads();

        float gi = gbuf[eb * 256 + ej];
        float gf = gbuf[eb * 256 + 64 + ej];
        float gg = gbuf[eb * 256 + 128 + ej];
        float go = gbuf[eb * 256 + 192 + ej];
        float i_ = sig_ap(gi), f_ = sig_ap(gf), g_ = tanh_ap(gg), o_ = sig_ap(go);
        c_reg = f_ * c_reg + i_ * g_;
        float h_ = o_ * tanh_ap(c_reg);
        inp[(128 + ej) * 4 + eb] = h_;
        inp[pk * 4 + pb]       = xpre.x;
        inp[(pk + 1) * 4 + pb] = xpre.y;
        __syncthreads();

        if (t == TT - 1) g_henc[(bb + eb) * HH + ej] = h_;
    }
}

// ---------------- decoder ----------------
// 128 CTAs x 4 batch rows, 512 threads.
// SMEM: Wd[64][384]x2 196608B | xp[512][4] 8192B | gbuf[4][512] 8192B | hsm[128][4] 2048B
#define DEC_SMEM_FLOATS (KD*384 + 4*GD + 4*GD + KD*4)
#define DEC_SMEM_BYTES  (DEC_SMEM_FLOATS * 4)

__global__ __launch_bounds__(512, 1)
void dec_kernel(const float* __restrict__ b_d, float* __restrict__ out) {
    extern __shared__ float sm[];
    float* Wd   = sm;                 // 49152 (k-paired)
    float* xp   = sm + KD * 384;      // 2048 [j][b]
    float* gbuf = xp + 4 * GD;        // 2048 [b][j]
    float* hsm  = gbuf + 4 * GD;      // 512  [k][b]

    const int tid = threadIdx.x;
    const int bb  = blockIdx.x * 4;

    {
        const float4* src = (const float4*)g_Wdec_t;
        float4* dst = (float4*)Wd;
        #pragma unroll 4
        for (int i = tid; i < (KD * 384) / 4; i += 512) dst[i] = src[i];
    }
    // stage h_enc[4][64] in gbuf[0..255]
    if (tid < 256) gbuf[tid] = g_henc[(bb + (tid >> 6)) * HH + (tid & 63)];
    hsm[tid] = 0.0f;
    __syncthreads();

    // one-time input projection -> xp (transposed [j][b] for v2.u64 reload)
    {
        const int j = tid;
        float a0 = b_d[j], a1 = a0, a2 = a0, a3 = a0;
        #pragma unroll 4
        for (int k = 0; k < HH; ++k) {
            float w = g_Wihd_t[k * GD + j];
            a0 = fmaf(w, gbuf[k], a0);
            a1 = fmaf(w, gbuf[64 + k], a1);
            a2 = fmaf(w, gbuf[128 + k], a2);
            a3 = fmaf(w, gbuf[192 + k], a3);
        }
        float4* xpv = (float4*)&xp[j * 4];
        *xpv = make_float4(a0, a1, a2, a3);
    }
    __syncthreads();

    float c_reg = 0.0f;
    const int eb = tid >> 7, ej = tid & 127;
    const unsigned Hb = (unsigned)__cvta_generic_to_shared(hsm);
    const unsigned Xb = (unsigned)__cvta_generic_to_shared(xp) + tid * 16;
    const unsigned Wb = (unsigned)__cvta_generic_to_shared(Wd) + tid * 8;
    const int jo = tid - 384;
    const float4* Wo = (const float4*)g_Wo4 + (jo >= 0 ? jo : 0);

    for (int t = 0; t < TT; ++t) {
        u64t a01, a23;
        lds_v2u64(a01, a23, Xb);                // gate bias (xp) for 4 batches

        if (tid < 384) {
            // i,f,g gates from SMEM weights
            unsigned wa = Wb, ha = Hb;
            #pragma unroll 8
            for (int k2 = 0; k2 < 64; ++k2) {
                float2 w = lds_f2(wa);
                u64t h0a, h0b, h1a, h1b;
                lds_v2u64(h0a, h0b, ha);
                lds_v2u64(h1a, h1b, ha + 16);
                u64t w0 = d2(w.x), w1 = d2(w.y);
                a01 = fma2(w0, h0a, a01); a23 = fma2(w0, h0b, a23);
                a01 = fma2(w1, h1a, a01); a23 = fma2(w1, h1b, a23);
                wa += 384 * 8;  // 3072
                ha += 32;
            }
        } else {
            // o-gate: weights streamed from L2 (64KB, hot), LDG.128 over 4 k
            unsigned ha = Hb;
            #pragma unroll 8
            for (int k4 = 0; k4 < 32; ++k4) {
                float4 w = __ldg(&Wo[k4 * 128]);
                u64t pa, pb;
                lds_v2u64(pa, pb, ha);
                a01 = fma2(d2(w.x), pa, a01); a23 = fma2(d2(w.x), pb, a23);
                lds_v2u64(pa, pb, ha + 16);
                a01 = fma2(d2(w.y), pa, a01); a23 = fma2(d2(w.y), pb, a23);
                lds_v2u64(pa, pb, ha + 32);
                a01 = fma2(d2(w.z), pa, a01); a23 = fma2(d2(w.z), pb, a23);
                lds_v2u64(pa, pb, ha + 48);
                a01 = fma2(d2(w.w), pa, a01); a23 = fma2(d2(w.w), pb, a23);
                ha += 64;
            }
        }
        float2 v01 = unpk(a01), v23 = unpk(a23);
        gbuf[tid] = v01.x; gbuf[512 + tid] = v01.y;
        gbuf[1024 + tid] = v23.x; gbuf[1536 + tid] = v23.y;
        __syncthreads();

        float gi = gbuf[eb * 512 + ej];
        float gf = gbuf[eb * 512 + 128 + ej];
        float gg = gbuf[eb * 512 + 256 + ej];
        float go = gbuf[eb * 512 + 384 + ej];
        float i_ = sig_ap(gi), f_ = sig_ap(gf), g_ = tanh_ap(gg), o_ = sig_ap(go);
        c_reg = f_ * c_reg + i_ * g_;
        float h_ = o_ * tanh_ap(c_reg);
        hsm[ej * 4 + eb] = h_;
        out[((size_t)(bb + eb) * TT + t) * DD + ej] = h_;
        __syncthreads();
    }
}

// ---------------- launch ----------------
extern "C" void kernel_launch(void* const* d_in, const int* in_sizes, int n_in,
                              void* d_out, int out_size) {
    const float* x     = (const float*)d_in[0];
    const float* Wih_e = (const float*)d_in[1];
    const float* Whh_e = (const float*)d_in[2];
    const float* b_e   = (const float*)d_in[3];
    const float* Wih_d = (const float*)d_in[4];
    const float* Whh_d = (const float*)d_in[5];
    const float* b_d   = (const float*)d_in[6];
    float* out = (float*)d_out;

    cudaFuncSetAttribute(enc_kernel, cudaFuncAttributeMaxDynamicSharedMemorySize, ENC_SMEM_BYTES);
    cudaFuncSetAttribute(dec_kernel, cudaFuncAttributeMaxDynamicSharedMemorySize, DEC_SMEM_BYTES);

    prep_kernel<<<576, 256>>>(Wih_e, Whh_e, Whh_d, Wih_d);
    enc_kernel<<<BATCH / 4, 256, ENC_SMEM_BYTES>>>(x, b_e);
    dec_kernel<<<BATCH / 4, 512, DEC_SMEM_BYTES>>>(b_d, out);
}